// round 15
// baseline (speedup 1.0000x reference)
#include <cuda_runtime.h>

// PathGuidedAggregator:
//   out[i,:] = (deg[i] <= 5) ? (sum_{e: rows[e]==i} embeds[cols[e],:]) / max(count_i,1) : 0
// Inputs int32 (JAX x64 disabled). rows SORTED.
// R14 = R8 design + streaming stores:
// (1) fused prep kernel = CSR boundary scatter + float4 zero-fill of the
//     whole output; sparse rows get overwritten by the gather kernel.
// (2) gather kernel: warp-per-row, dense rows exit after ONE degree load (no
//     store), unroll-8 LDG.128 for MLP=8 per warp.
// (3) __stcs on all output stores (write-only stream, evict-first) so the
//     51 MB output doesn't evict the 51 MB embed table from L2 during gather.

#define EMBED_DIM 128
#define SPARSE_THRESHOLD 5
#define MAX_ENT 100000
#define WARPS_PER_BLOCK 8
#define BLOCK_THREADS (WARPS_PER_BLOCK * 32)

__device__ int g_start[MAX_ENT];  // zero-init at load; rewrites idempotent per replay
__device__ int g_end[MAX_ENT];

// Fused: boundary scatter over sorted rows + zero-fill of out (all rows).
__global__ void prep_kernel(const int* __restrict__ rows, int n_edges,
                            float4* __restrict__ out4, int n_vec) {
    const int t = blockIdx.x * blockDim.x + threadIdx.x;
    if (t < n_edges) {
        const int r = __ldg(&rows[t]);
        if (t == 0 || __ldg(&rows[t - 1]) != r) g_start[r] = t;
        if (t == n_edges - 1 || __ldg(&rows[t + 1]) != r) g_end[r] = t + 1;
    }
    if (t < n_vec) {
        __stcs(&out4[t], make_float4(0.f, 0.f, 0.f, 0.f));
    }
}

__global__ void __launch_bounds__(BLOCK_THREADS)
gather_kernel(const float* __restrict__ embeds,
              const int* __restrict__ degrees,
              const int* __restrict__ cols,
              float* __restrict__ out,
              int n_ent) {
    const int row  = blockIdx.x * WARPS_PER_BLOCK + (threadIdx.x >> 5);
    const int lane = threadIdx.x & 31;
    if (row >= n_ent) return;

    // Dense row: already zeroed by prep_kernel — exit with no store.
    if (__ldg(&degrees[row]) > SPARSE_THRESHOLD) return;

    const int start = __ldg(&g_start[row]);
    const int end   = __ldg(&g_end[row]);

    float4 a0 = make_float4(0.f, 0.f, 0.f, 0.f);
    float4 a1 = make_float4(0.f, 0.f, 0.f, 0.f);
    float4 a2 = make_float4(0.f, 0.f, 0.f, 0.f);
    float4 a3 = make_float4(0.f, 0.f, 0.f, 0.f);

    for (int base = start; base < end; base += 32) {
        const int m = min(32, end - base);
        // One coalesced col load covers up to 32 edges; broadcast via shfl.
        const int mycol = (lane < m) ? __ldg(&cols[base + lane]) : 0;

        int e = 0;
        for (; e + 7 < m; e += 8) {
            const int c0 = __shfl_sync(0xffffffffu, mycol, e + 0);
            const int c1 = __shfl_sync(0xffffffffu, mycol, e + 1);
            const int c2 = __shfl_sync(0xffffffffu, mycol, e + 2);
            const int c3 = __shfl_sync(0xffffffffu, mycol, e + 3);
            const int c4 = __shfl_sync(0xffffffffu, mycol, e + 4);
            const int c5 = __shfl_sync(0xffffffffu, mycol, e + 5);
            const int c6 = __shfl_sync(0xffffffffu, mycol, e + 6);
            const int c7 = __shfl_sync(0xffffffffu, mycol, e + 7);
            const float4 v0 = __ldg((const float4*)(embeds + (size_t)c0 * EMBED_DIM) + lane);
            const float4 v1 = __ldg((const float4*)(embeds + (size_t)c1 * EMBED_DIM) + lane);
            const float4 v2 = __ldg((const float4*)(embeds + (size_t)c2 * EMBED_DIM) + lane);
            const float4 v3 = __ldg((const float4*)(embeds + (size_t)c3 * EMBED_DIM) + lane);
            const float4 v4 = __ldg((const float4*)(embeds + (size_t)c4 * EMBED_DIM) + lane);
            const float4 v5 = __ldg((const float4*)(embeds + (size_t)c5 * EMBED_DIM) + lane);
            const float4 v6 = __ldg((const float4*)(embeds + (size_t)c6 * EMBED_DIM) + lane);
            const float4 v7 = __ldg((const float4*)(embeds + (size_t)c7 * EMBED_DIM) + lane);
            a0.x += v0.x; a0.y += v0.y; a0.z += v0.z; a0.w += v0.w;
            a1.x += v1.x; a1.y += v1.y; a1.z += v1.z; a1.w += v1.w;
            a2.x += v2.x; a2.y += v2.y; a2.z += v2.z; a2.w += v2.w;
            a3.x += v3.x; a3.y += v3.y; a3.z += v3.z; a3.w += v3.w;
            a0.x += v4.x; a0.y += v4.y; a0.z += v4.z; a0.w += v4.w;
            a1.x += v5.x; a1.y += v5.y; a1.z += v5.z; a1.w += v5.w;
            a2.x += v6.x; a2.y += v6.y; a2.z += v6.z; a2.w += v6.w;
            a3.x += v7.x; a3.y += v7.y; a3.z += v7.z; a3.w += v7.w;
        }
        for (; e + 3 < m; e += 4) {
            const int c0 = __shfl_sync(0xffffffffu, mycol, e + 0);
            const int c1 = __shfl_sync(0xffffffffu, mycol, e + 1);
            const int c2 = __shfl_sync(0xffffffffu, mycol, e + 2);
            const int c3 = __shfl_sync(0xffffffffu, mycol, e + 3);
            const float4 v0 = __ldg((const float4*)(embeds + (size_t)c0 * EMBED_DIM) + lane);
            const float4 v1 = __ldg((const float4*)(embeds + (size_t)c1 * EMBED_DIM) + lane);
            const float4 v2 = __ldg((const float4*)(embeds + (size_t)c2 * EMBED_DIM) + lane);
            const float4 v3 = __ldg((const float4*)(embeds + (size_t)c3 * EMBED_DIM) + lane);
            a0.x += v0.x; a0.y += v0.y; a0.z += v0.z; a0.w += v0.w;
            a1.x += v1.x; a1.y += v1.y; a1.z += v1.z; a1.w += v1.w;
            a2.x += v2.x; a2.y += v2.y; a2.z += v2.z; a2.w += v2.w;
            a3.x += v3.x; a3.y += v3.y; a3.z += v3.z; a3.w += v3.w;
        }
        for (; e < m; ++e) {
            const int c = __shfl_sync(0xffffffffu, mycol, e);
            const float4 v = __ldg((const float4*)(embeds + (size_t)c * EMBED_DIM) + lane);
            a0.x += v.x; a0.y += v.y; a0.z += v.z; a0.w += v.w;
        }
    }

    float4 acc;
    acc.x = (a0.x + a1.x) + (a2.x + a3.x);
    acc.y = (a0.y + a1.y) + (a2.y + a3.y);
    acc.z = (a0.z + a1.z) + (a2.z + a3.z);
    acc.w = (a0.w + a1.w) + (a2.w + a3.w);

    const int cnt = end - start;
    const float inv = 1.0f / (float)(cnt > 0 ? cnt : 1);
    acc.x *= inv; acc.y *= inv; acc.z *= inv; acc.w *= inv;
    __stcs((float4*)(out + (size_t)row * EMBED_DIM) + lane, acc);
}

extern "C" void kernel_launch(void* const* d_in, const int* in_sizes, int n_in,
                              void* d_out, int out_size) {
    const float* embeds  = (const float*)d_in[0];  // [N_ENT, 128] fp32
    const int*   degrees = (const int*)d_in[1];    // [N_ENT] int32
    const int*   rows    = (const int*)d_in[2];    // [N_EDGES] int32, sorted
    const int*   cols    = (const int*)d_in[3];    // [N_EDGES] int32
    float*       out     = (float*)d_out;          // [N_ENT, 128] fp32

    const int n_ent   = in_sizes[1];
    const int n_edges = in_sizes[2];
    const int n_vec   = n_ent * (EMBED_DIM / 4);   // out as float4s

    const int n_prep  = (n_edges > n_vec) ? n_edges : n_vec;
    prep_kernel<<<(n_prep + 255) / 256, 256>>>(rows, n_edges, (float4*)d_out, n_vec);
    gather_kernel<<<(n_ent + WARPS_PER_BLOCK - 1) / WARPS_PER_BLOCK, BLOCK_THREADS>>>(
        embeds, degrees, cols, out, n_ent);
}

// round 17
// speedup vs baseline: 1.2581x; 1.2581x over previous
#include <cuda_runtime.h>

// PathGuidedAggregator:
//   out[i,:] = (deg[i] <= 5) ? (sum_{e: rows[e]==i} embeds[cols[e],:]) / max(count_i,1) : 0
// Inputs int32 (JAX x64 disabled). rows SORTED.
// R15 design (resubmit after broker timeout): worklist-compacted gather.
// R14's gather had ~1.2 working warps per resident CTA (dense warps exited
// but CTA regs stayed pinned) -> ~5 working warps/SM -> latency-bound at
// L2 22.9%. Prep builds a compacted list of sparse rows; gather runs ONE
// worklist entry per warp -> resident CTAs are 8/8 working warps (~6x
// outstanding loads). Blocks beyond nwork exit instantly.

#define EMBED_DIM 128
#define SPARSE_THRESHOLD 5
#define MAX_ENT 100000
#define WARPS_PER_BLOCK 8
#define BLOCK_THREADS (WARPS_PER_BLOCK * 32)

__device__ int g_start[MAX_ENT];  // zero-init at load; rewrites idempotent per replay
__device__ int g_end[MAX_ENT];
__device__ int g_work[MAX_ENT];
__device__ int g_nwork;

__global__ void reset_kernel() { g_nwork = 0; }

// Fused prep: CSR boundary scatter + worklist build + zero-fill of out.
__global__ void prep_kernel(const int* __restrict__ rows,
                            const int* __restrict__ degrees,
                            int n_edges, int n_ent,
                            float4* __restrict__ out4, int n_vec) {
    const int t = blockIdx.x * blockDim.x + threadIdx.x;
    if (t < n_edges) {
        const int r = __ldg(&rows[t]);
        if (t == 0 || __ldg(&rows[t - 1]) != r) g_start[r] = t;
        if (t == n_edges - 1 || __ldg(&rows[t + 1]) != r) g_end[r] = t + 1;
    }
    if (t < n_ent) {
        if (__ldg(&degrees[t]) <= SPARSE_THRESHOLD) {
            const int pos = atomicAdd(&g_nwork, 1);
            g_work[pos] = t;
        }
    }
    if (t < n_vec) {
        __stcs(&out4[t], make_float4(0.f, 0.f, 0.f, 0.f));
    }
}

__global__ void __launch_bounds__(BLOCK_THREADS)
gather_kernel(const float* __restrict__ embeds,
              const int* __restrict__ cols,
              float* __restrict__ out) {
    const int w    = blockIdx.x * WARPS_PER_BLOCK + (threadIdx.x >> 5);
    const int lane = threadIdx.x & 31;

    if (w >= g_nwork) return;          // beyond worklist: exit, free CTA fast
    const int row = g_work[w];

    const int start = __ldg(&g_start[row]);
    const int end   = __ldg(&g_end[row]);

    float4 a0 = make_float4(0.f, 0.f, 0.f, 0.f);
    float4 a1 = make_float4(0.f, 0.f, 0.f, 0.f);
    float4 a2 = make_float4(0.f, 0.f, 0.f, 0.f);
    float4 a3 = make_float4(0.f, 0.f, 0.f, 0.f);

    for (int base = start; base < end; base += 32) {
        const int m = min(32, end - base);
        // One coalesced col load covers up to 32 edges; broadcast via shfl.
        const int mycol = (lane < m) ? __ldg(&cols[base + lane]) : 0;

        int e = 0;
        for (; e + 7 < m; e += 8) {
            const int c0 = __shfl_sync(0xffffffffu, mycol, e + 0);
            const int c1 = __shfl_sync(0xffffffffu, mycol, e + 1);
            const int c2 = __shfl_sync(0xffffffffu, mycol, e + 2);
            const int c3 = __shfl_sync(0xffffffffu, mycol, e + 3);
            const int c4 = __shfl_sync(0xffffffffu, mycol, e + 4);
            const int c5 = __shfl_sync(0xffffffffu, mycol, e + 5);
            const int c6 = __shfl_sync(0xffffffffu, mycol, e + 6);
            const int c7 = __shfl_sync(0xffffffffu, mycol, e + 7);
            const float4 v0 = __ldg((const float4*)(embeds + (size_t)c0 * EMBED_DIM) + lane);
            const float4 v1 = __ldg((const float4*)(embeds + (size_t)c1 * EMBED_DIM) + lane);
            const float4 v2 = __ldg((const float4*)(embeds + (size_t)c2 * EMBED_DIM) + lane);
            const float4 v3 = __ldg((const float4*)(embeds + (size_t)c3 * EMBED_DIM) + lane);
            const float4 v4 = __ldg((const float4*)(embeds + (size_t)c4 * EMBED_DIM) + lane);
            const float4 v5 = __ldg((const float4*)(embeds + (size_t)c5 * EMBED_DIM) + lane);
            const float4 v6 = __ldg((const float4*)(embeds + (size_t)c6 * EMBED_DIM) + lane);
            const float4 v7 = __ldg((const float4*)(embeds + (size_t)c7 * EMBED_DIM) + lane);
            a0.x += v0.x; a0.y += v0.y; a0.z += v0.z; a0.w += v0.w;
            a1.x += v1.x; a1.y += v1.y; a1.z += v1.z; a1.w += v1.w;
            a2.x += v2.x; a2.y += v2.y; a2.z += v2.z; a2.w += v2.w;
            a3.x += v3.x; a3.y += v3.y; a3.z += v3.z; a3.w += v3.w;
            a0.x += v4.x; a0.y += v4.y; a0.z += v4.z; a0.w += v4.w;
            a1.x += v5.x; a1.y += v5.y; a1.z += v5.z; a1.w += v5.w;
            a2.x += v6.x; a2.y += v6.y; a2.z += v6.z; a2.w += v6.w;
            a3.x += v7.x; a3.y += v7.y; a3.z += v7.z; a3.w += v7.w;
        }
        for (; e + 3 < m; e += 4) {
            const int c0 = __shfl_sync(0xffffffffu, mycol, e + 0);
            const int c1 = __shfl_sync(0xffffffffu, mycol, e + 1);
            const int c2 = __shfl_sync(0xffffffffu, mycol, e + 2);
            const int c3 = __shfl_sync(0xffffffffu, mycol, e + 3);
            const float4 v0 = __ldg((const float4*)(embeds + (size_t)c0 * EMBED_DIM) + lane);
            const float4 v1 = __ldg((const float4*)(embeds + (size_t)c1 * EMBED_DIM) + lane);
            const float4 v2 = __ldg((const float4*)(embeds + (size_t)c2 * EMBED_DIM) + lane);
            const float4 v3 = __ldg((const float4*)(embeds + (size_t)c3 * EMBED_DIM) + lane);
            a0.x += v0.x; a0.y += v0.y; a0.z += v0.z; a0.w += v0.w;
            a1.x += v1.x; a1.y += v1.y; a1.z += v1.z; a1.w += v1.w;
            a2.x += v2.x; a2.y += v2.y; a2.z += v2.z; a2.w += v2.w;
            a3.x += v3.x; a3.y += v3.y; a3.z += v3.z; a3.w += v3.w;
        }
        for (; e < m; ++e) {
            const int c = __shfl_sync(0xffffffffu, mycol, e);
            const float4 v = __ldg((const float4*)(embeds + (size_t)c * EMBED_DIM) + lane);
            a0.x += v.x; a0.y += v.y; a0.z += v.z; a0.w += v.w;
        }
    }

    float4 acc;
    acc.x = (a0.x + a1.x) + (a2.x + a3.x);
    acc.y = (a0.y + a1.y) + (a2.y + a3.y);
    acc.z = (a0.z + a1.z) + (a2.z + a3.z);
    acc.w = (a0.w + a1.w) + (a2.w + a3.w);

    const int cnt = end - start;
    const float inv = 1.0f / (float)(cnt > 0 ? cnt : 1);
    acc.x *= inv; acc.y *= inv; acc.z *= inv; acc.w *= inv;
    __stcs((float4*)(out + (size_t)row * EMBED_DIM) + lane, acc);
}

extern "C" void kernel_launch(void* const* d_in, const int* in_sizes, int n_in,
                              void* d_out, int out_size) {
    const float* embeds  = (const float*)d_in[0];  // [N_ENT, 128] fp32
    const int*   degrees = (const int*)d_in[1];    // [N_ENT] int32
    const int*   rows    = (const int*)d_in[2];    // [N_EDGES] int32, sorted
    const int*   cols    = (const int*)d_in[3];    // [N_EDGES] int32
    float*       out     = (float*)d_out;          // [N_ENT, 128] fp32

    const int n_ent   = in_sizes[1];
    const int n_edges = in_sizes[2];
    const int n_vec   = n_ent * (EMBED_DIM / 4);   // out as float4s

    const int n_prep  = (n_edges > n_vec) ? n_edges : n_vec;
    reset_kernel<<<1, 1>>>();
    prep_kernel<<<(n_prep + 255) / 256, 256>>>(rows, degrees, n_edges, n_ent,
                                               (float4*)d_out, n_vec);
    // Worst case: all rows sparse -> one warp per row.
    gather_kernel<<<(n_ent + WARPS_PER_BLOCK - 1) / WARPS_PER_BLOCK, BLOCK_THREADS>>>(
        embeds, cols, out);
}